// round 4
// baseline (speedup 1.0000x reference)
#include <cuda_runtime.h>
#include <cstdint>

#define N_FFT   4096
#define THREADS 512
#define SKEW(i) ((i) + ((i) >> 4))
#define BUF_ELEMS (N_FFT + (N_FFT >> 4))   // 4352 float2 = 34816 B static smem

__device__ __forceinline__ float2 cadd(float2 a, float2 b){ return make_float2(a.x+b.x, a.y+b.y); }
__device__ __forceinline__ float2 csub(float2 a, float2 b){ return make_float2(a.x-b.x, a.y-b.y); }
__device__ __forceinline__ float2 cmul(float2 a, float2 b){
    return make_float2(fmaf(a.x, b.x, -a.y*b.y), fmaf(a.x, b.y, a.y*b.x));
}
// multiply by +i
__device__ __forceinline__ float2 cmuli(float2 a){ return make_float2(-a.y, a.x); }

// reverse 4 octal digits of a 12-bit index
__device__ __forceinline__ int drev(int v) {
    return ((v & 7) << 9) | (((v >> 3) & 7) << 6) | (((v >> 6) & 7) << 3) | ((v >> 9) & 7);
}

// One in-place radix-8 DIF butterfly (positive-sign DFT), sub-transform length L.
// Reads/writes the 8 private slots {B + p + j*m}, j=0..7  (m = L/8).
template<int L>
__device__ __forceinline__ void radix8_stage(float2* buf, int B, int p, int m) {
    float2 a[8];
#pragma unroll
    for (int j = 0; j < 8; j++) a[j] = buf[SKEW(B + p + j * m)];

    // 8-point DFT, omega8 = e^{+2*pi*i/8}
    float2 t0 = cadd(a[0], a[4]);
    float2 t1 = csub(a[0], a[4]);
    float2 t2 = cadd(a[2], a[6]);
    float2 t3 = cmuli(csub(a[2], a[6]));
    float2 u0 = cadd(a[1], a[5]);
    float2 u1 = csub(a[1], a[5]);
    float2 u2 = cadd(a[3], a[7]);
    float2 u3 = cmuli(csub(a[3], a[7]));

    float2 E0 = cadd(t0, t2), E2 = csub(t0, t2);
    float2 E1 = cadd(t1, t3), E3 = csub(t1, t3);
    float2 O0 = cadd(u0, u2), O2 = csub(u0, u2);
    float2 O1 = cadd(u1, u3), O3 = csub(u1, u3);

    const float r = 0.7071067811865476f;
    float2 W1 = make_float2(r * (O1.x - O1.y),  r * (O1.x + O1.y));   // omega8^1 * O1
    float2 W2 = cmuli(O2);                                            // omega8^2 * O2
    float2 W3 = make_float2(-r * (O3.x + O3.y), r * (O3.x - O3.y));   // omega8^3 * O3

    float2 b[8];
    b[0] = cadd(E0, O0); b[4] = csub(E0, O0);
    b[1] = cadd(E1, W1); b[5] = csub(E1, W1);
    b[2] = cadd(E2, W2); b[6] = csub(E2, W2);
    b[3] = cadd(E3, W3); b[7] = csub(E3, W3);

    if (L > 8) {
        // w1 = e^{+2*pi*i*p/L}; exact pi-scaled arg (p * 2/L is a power-of-two scale)
        float s1, c1;
        sincospif((float)p * (2.0f / (float)L), &s1, &c1);
        float2 w1 = make_float2(c1, s1);
        float2 w  = w1;
#pragma unroll
        for (int j = 1; j < 8; j++) {
            b[j] = cmul(b[j], w);
            if (j < 7) w = cmul(w, w1);
        }
    }
#pragma unroll
    for (int j = 0; j < 8; j++) buf[SKEW(B + p + j * m)] = b[j];
}

__global__ void __launch_bounds__(THREADS, 2)
idct_fft_kernel(const float* __restrict__ x, float* __restrict__ y) {
    __shared__ float2 buf[BUF_ELEMS];
    const int t = threadIdx.x;
    const size_t rowoff = (size_t)blockIdx.x * N_FFT;

    // ---- load row (coalesced float4) into smem as plain floats ----
    {
        const float4* r4 = (const float4*)(x + rowoff);
        float4*       s4 = (float4*)buf;
        s4[t]           = r4[t];
        s4[t + THREADS] = r4[t + THREADS];
    }
    __syncthreads();

    // ---- build V_k = e^{i*pi*k/(2N)} * (x_k - i*x_{N-k}) in registers ----
    // Pairs: thread covers k in [0,2048) and partner N-k via V_{N-k} = conj(V_k).
    // Specials: V_0 = x_0 (real), V_{N/2} = sqrt(2)*x_{N/2} (real).
    const float* xs = (const float*)buf;
    float vr[4], vi[4], pr[4], pim[4];
    int   pj[4];
#pragma unroll
    for (int i = 0; i < 4; i++) {
        int   k  = t + THREADS * i;                       // 0..2047
        float xk = xs[k];
        float xq = xs[(N_FFT - k) & (N_FFT - 1)];
        float s, c;
        sincospif((float)k * (1.0f / (2.0f * N_FFT)), &s, &c);  // sin/cos(pi*k/2N)
        float re = fmaf(c, xk,  s * xq);
        float im = fmaf(s, xk, -c * xq);
        if (k == 0) {
            vr[i] = xk;                           vi[i]  = 0.0f;
            pr[i] = 1.4142135623730951f * xs[N_FFT / 2]; pim[i] = 0.0f;
            pj[i] = N_FFT / 2;
        } else {
            vr[i] = re;  vi[i]  = im;
            pr[i] = re;  pim[i] = -im;
            pj[i] = N_FFT - k;
        }
    }
    __syncthreads();   // all xs reads done before overwriting with complex V
#pragma unroll
    for (int i = 0; i < 4; i++) {
        int k = t + THREADS * i;
        buf[SKEW(k)]     = make_float2(vr[i], vi[i]);
        buf[SKEW(pj[i])] = make_float2(pr[i], pim[i]);
    }
    __syncthreads();

    // ---- 4 in-place radix-8 DIF stages (positive sign); output digit-reversed ----
    radix8_stage<4096>(buf, 0,               t,       512);
    __syncthreads();
    radix8_stage<512 >(buf, (t >> 6) << 9,   t & 63,  64);
    __syncthreads();
    radix8_stage<64  >(buf, (t >> 3) << 6,   t & 7,   8);
    __syncthreads();
    radix8_stage<8   >(buf, t << 3,          0,       1);
    __syncthreads();

    // ---- epilogue: v_m lives at storage drev(m); y_{2m}=v_m, y_{2m+1}=v_{N-1-m}.
    // Adjacent output pair -> fully coalesced float2 stores.
    float2* o2 = (float2*)(y + rowoff);
#pragma unroll
    for (int i = 0; i < 4; i++) {
        int   mI = t + THREADS * i;                 // 0..2047
        float a  = buf[SKEW(drev(mI))].x;
        float b  = buf[SKEW(drev(N_FFT - 1 - mI))].x;
        o2[mI] = make_float2(a, b);
    }
}

extern "C" void kernel_launch(void* const* d_in, const int* in_sizes, int n_in,
                              void* d_out, int out_size) {
    const float* x = (const float*)d_in[0];
    float*       y = (float*)d_out;
    int rows = in_sizes[0] / N_FFT;      // 4096 for this problem
    idct_fft_kernel<<<rows, THREADS>>>(x, y);
}

// round 6
// speedup vs baseline: 1.0887x; 1.0887x over previous
#include <cuda_runtime.h>
#include <cstdint>

#define N_FFT   4096
#define THREADS 512
#define SKEW(i) ((i) + ((i) >> 4))
#define BUF_ELEMS (N_FFT + (N_FFT >> 4))   // 4352 float2 = 34816 B static smem
#define SWZ(i)  ((i) ^ (((i) >> 6) & 7))   // XOR swizzle for the real-only buffer

__device__ __forceinline__ float2 cadd(float2 a, float2 b){ return make_float2(a.x+b.x, a.y+b.y); }
__device__ __forceinline__ float2 csub(float2 a, float2 b){ return make_float2(a.x-b.x, a.y-b.y); }
__device__ __forceinline__ float2 cmul(float2 a, float2 b){
    return make_float2(fmaf(a.x, b.x, -a.y*b.y), fmaf(a.x, b.y, a.y*b.x));
}
__device__ __forceinline__ float2 cmuli(float2 a){ return make_float2(-a.y, a.x); }   // *(+i)

// 8-point DFT core, omega8 = e^{+2*pi*i/8}  (positive-sign DFT)
__device__ __forceinline__ void dft8(const float2 a[8], float2 b[8]) {
    float2 t0 = cadd(a[0], a[4]);
    float2 t1 = csub(a[0], a[4]);
    float2 t2 = cadd(a[2], a[6]);
    float2 t3 = cmuli(csub(a[2], a[6]));
    float2 u0 = cadd(a[1], a[5]);
    float2 u1 = csub(a[1], a[5]);
    float2 u2 = cadd(a[3], a[7]);
    float2 u3 = cmuli(csub(a[3], a[7]));

    float2 E0 = cadd(t0, t2), E2 = csub(t0, t2);
    float2 E1 = cadd(t1, t3), E3 = csub(t1, t3);
    float2 O0 = cadd(u0, u2), O2 = csub(u0, u2);
    float2 O1 = cadd(u1, u3), O3 = csub(u1, u3);

    const float r = 0.7071067811865476f;
    float2 W1 = make_float2(r * (O1.x - O1.y),  r * (O1.x + O1.y));   // omega8^1 * O1
    float2 W2 = cmuli(O2);                                            // omega8^2 * O2
    float2 W3 = make_float2(-r * (O3.x + O3.y), r * (O3.x - O3.y));   // omega8^3 * O3

    b[0] = cadd(E0, O0); b[4] = csub(E0, O0);
    b[1] = cadd(E1, W1); b[5] = csub(E1, W1);
    b[2] = cadd(E2, W2); b[6] = csub(E2, W2);
    b[3] = cadd(E3, W3); b[7] = csub(E3, W3);
}

// post-butterfly twiddles for sub-transform length L: b[j] *= e^{+2*pi*i*p*j/L}
template<int L>
__device__ __forceinline__ void twiddle8(float2 b[8], int p) {
    if (L > 8) {
        float s1, c1;
        sincospif((float)p * (2.0f / (float)L), &s1, &c1);   // exact pi-scaled arg
        float2 w1 = make_float2(c1, s1);
        float2 w  = w1;
#pragma unroll
        for (int j = 1; j < 8; j++) {
            b[j] = cmul(b[j], w);
            if (j < 7) w = cmul(w, w1);
        }
    }
}

__global__ void __launch_bounds__(THREADS, 2)
idct_fft_kernel(const float* __restrict__ x, float* __restrict__ y) {
    __shared__ float2 buf[BUF_ELEMS];
    const int t = threadIdx.x;
    const size_t rowoff = (size_t)blockIdx.x * N_FFT;
    const float* __restrict__ xr = x + rowoff;

    float2 a[8], b[8];

    // ---- stage 1 fused with V-build, sourcing x directly from global ----
    // V_k = e^{i*pi*k/(2N)} * (x_k - i*x_{N-k});  valid for all k>=1 (conjugate
    // symmetry is implied by the formula itself); V_0 = x_0 is the only special.
#pragma unroll
    for (int j = 0; j < 8; j++) {
        int   k  = t + 512 * j;
        float xk = __ldg(xr + k);
        float xq = __ldg(xr + ((N_FFT - k) & (N_FFT - 1)));
        float s, c;
        sincospif((float)k * (1.0f / (2.0f * N_FFT)), &s, &c);   // sin/cos(pi*k/2N)
        a[j].x = fmaf(c, xk,  s * xq);
        a[j].y = fmaf(s, xk, -c * xq);
    }
    if (t == 0) { a[0].x = __ldg(xr); a[0].y = 0.0f; }
    dft8(a, b);
    twiddle8<4096>(b, t);
#pragma unroll
    for (int j = 0; j < 8; j++) buf[SKEW(t + 512 * j)] = b[j];
    __syncthreads();

    // ---- stage 2 (L = 512, stride 64) ----
    {
        const int B = (t >> 6) << 9, p = t & 63;
#pragma unroll
        for (int j = 0; j < 8; j++) a[j] = buf[SKEW(B + p + 64 * j)];
        dft8(a, b);
        twiddle8<512>(b, p);
#pragma unroll
        for (int j = 0; j < 8; j++) buf[SKEW(B + p + 64 * j)] = b[j];
    }
    __syncthreads();

    // ---- stage 3 (L = 64, stride 8) ----
    {
        const int B = (t >> 3) << 6, p = t & 7;
#pragma unroll
        for (int j = 0; j < 8; j++) a[j] = buf[SKEW(B + p + 8 * j)];
        dft8(a, b);
        twiddle8<64>(b, p);
#pragma unroll
        for (int j = 0; j < 8; j++) buf[SKEW(B + p + 8 * j)] = b[j];
    }
    __syncthreads();

    // ---- stage 4 (L = 8) fused with digit-reversal scatter ----
#pragma unroll
    for (int j = 0; j < 8; j++) a[j] = buf[SKEW(8 * t + j)];
    __syncthreads();                 // all stage-4 reads done before aliasing overwrite
    dft8(a, b);                      // no twiddles at L = 8

    // b[j].x = v at storage index 8t+j -> logical m = drev(8t+j) = base + 512j.
    // Scatter REAL parts into an aliased float buffer at logical index m,
    // XOR-swizzled: bank = ((t>>6)^(lane&7)) | (((lane>>3)&3)<<3) -> conflict-free.
    float* vre = (float*)buf;
    {
        const int base = 64 * (t & 7) + 8 * ((t >> 3) & 7) + (t >> 6);
#pragma unroll
        for (int j = 0; j < 8; j++) {
            int m = base + 512 * j;
            vre[SWZ(m)] = b[j].x;
        }
    }
    __syncthreads();

    // ---- gather pairs: thread t owns m = 4t..4t+3 (2048 pairs / 512 threads).
    // y_{2m} = v_m, y_{2m+1} = v_{N-1-m}  ->  y[8t..8t+7], two STG.128.
    float va[4], vb[4];
#pragma unroll
    for (int c = 0; c < 4; c++) va[c] = vre[SWZ(4 * t + c)];
#pragma unroll
    for (int c = 0; c < 4; c++) vb[c] = vre[SWZ(N_FFT - 1 - 4 * t - c)];

    float4* o4 = (float4*)(y + rowoff);
    o4[2 * t]     = make_float4(va[0], vb[0], va[1], vb[1]);
    o4[2 * t + 1] = make_float4(va[2], vb[2], va[3], vb[3]);
}

extern "C" void kernel_launch(void* const* d_in, const int* in_sizes, int n_in,
                              void* d_out, int out_size) {
    (void)n_in; (void)out_size;
    const float* x = (const float*)d_in[0];
    float*       y = (float*)d_out;
    int rows = in_sizes[0] / N_FFT;      // 4096 for this problem
    idct_fft_kernel<<<rows, THREADS>>>(x, y);
}

// round 7
// speedup vs baseline: 1.1905x; 1.0936x over previous
#include <cuda_runtime.h>
#include <cstdint>

#define N_FFT   4096
#define THREADS 512
#define SKEW(i) ((i) + ((i) >> 4))
#define BUF_ELEMS (N_FFT + (N_FFT >> 4))   // 4352 float2 = 34816 B static smem
#define SWZ(i)  ((i) ^ (((i) >> 6) & 7))   // XOR swizzle for the real-only buffer

__device__ __forceinline__ float2 cadd(float2 a, float2 b){ return make_float2(a.x+b.x, a.y+b.y); }
__device__ __forceinline__ float2 csub(float2 a, float2 b){ return make_float2(a.x-b.x, a.y-b.y); }
__device__ __forceinline__ float2 cmul(float2 a, float2 b){
    return make_float2(fmaf(a.x, b.x, -a.y*b.y), fmaf(a.x, b.y, a.y*b.x));
}
__device__ __forceinline__ float2 cmuli(float2 a){ return make_float2(-a.y, a.x); }   // *(+i)

// 8-point DFT core, omega8 = e^{+2*pi*i/8}  (positive-sign DFT)
__device__ __forceinline__ void dft8(const float2 a[8], float2 b[8]) {
    float2 t0 = cadd(a[0], a[4]);
    float2 t1 = csub(a[0], a[4]);
    float2 t2 = cadd(a[2], a[6]);
    float2 t3 = cmuli(csub(a[2], a[6]));
    float2 u0 = cadd(a[1], a[5]);
    float2 u1 = csub(a[1], a[5]);
    float2 u2 = cadd(a[3], a[7]);
    float2 u3 = cmuli(csub(a[3], a[7]));

    float2 E0 = cadd(t0, t2), E2 = csub(t0, t2);
    float2 E1 = cadd(t1, t3), E3 = csub(t1, t3);
    float2 O0 = cadd(u0, u2), O2 = csub(u0, u2);
    float2 O1 = cadd(u1, u3), O3 = csub(u1, u3);

    const float r = 0.7071067811865476f;
    float2 W1 = make_float2(r * (O1.x - O1.y),  r * (O1.x + O1.y));   // omega8^1 * O1
    float2 W2 = cmuli(O2);                                            // omega8^2 * O2
    float2 W3 = make_float2(-r * (O3.x + O3.y), r * (O3.x - O3.y));   // omega8^3 * O3

    b[0] = cadd(E0, O0); b[4] = csub(E0, O0);
    b[1] = cadd(E1, W1); b[5] = csub(E1, W1);
    b[2] = cadd(E2, W2); b[6] = csub(E2, W2);
    b[3] = cadd(E3, W3); b[7] = csub(E3, W3);
}

// Apply twiddles b[j] *= w1^j using log-depth power generation.
__device__ __forceinline__ void twiddle8w(float2 b[8], float2 w1) {
    float2 w2 = cmul(w1, w1);
    float2 w3 = cmul(w2, w1);
    float2 w4 = cmul(w2, w2);
    float2 w5 = cmul(w3, w2);
    float2 w6 = cmul(w3, w3);
    float2 w7 = cmul(w4, w3);
    b[1] = cmul(b[1], w1);
    b[2] = cmul(b[2], w2);
    b[3] = cmul(b[3], w3);
    b[4] = cmul(b[4], w4);
    b[5] = cmul(b[5], w5);
    b[6] = cmul(b[6], w6);
    b[7] = cmul(b[7], w7);
}

__global__ void __launch_bounds__(THREADS, 2)
idct_fft_kernel(const float* __restrict__ x, float* __restrict__ y) {
    __shared__ float2 buf[BUF_ELEMS];
    const int t = threadIdx.x;
    const size_t rowoff = (size_t)blockIdx.x * N_FFT;
    const float* __restrict__ xr = x + rowoff;

    float2 a[8], b[8];

    // ---- stage 1 fused with V-build, sourcing x directly from global ----
    // V_k = e^{i*pi*k/(2N)} * (x_k - i*x_{N-k}), k = t + 512 j.
    // e^{i*pi*k/8192} = e0 * E_j, e0 = e^{i*pi*t/8192} (ONE sincos),
    // E_j = e^{i*pi*j/16} compile-time constants.
    {
        float s0, c0;
        __sincosf((float)t * 3.8349519697141028e-4f, &s0, &c0);  // pi/8192
        const float2 e0 = make_float2(c0, s0);
        const float EC[8] = { 1.0f, 0.9807852804032304f, 0.9238795325112868f,
                              0.8314696123025452f, 0.7071067811865476f,
                              0.5555702330196022f, 0.3826834323650898f,
                              0.1950903220161283f };
        const float ES[8] = { 0.0f, 0.1950903220161283f, 0.3826834323650898f,
                              0.5555702330196022f, 0.7071067811865476f,
                              0.8314696123025452f, 0.9238795325112868f,
                              0.9807852804032304f };
#pragma unroll
        for (int j = 0; j < 8; j++) {
            int   k  = t + 512 * j;
            float xk = __ldg(xr + k);
            float xq = __ldg(xr + ((N_FFT - k) & (N_FFT - 1)));
            // (c,s) = e0 * E_j
            float c = fmaf(e0.x, EC[j], -e0.y * ES[j]);
            float s = fmaf(e0.x, ES[j],  e0.y * EC[j]);
            a[j].x = fmaf(c, xk,  s * xq);
            a[j].y = fmaf(s, xk, -c * xq);
        }
        if (t == 0) { a[0].x = __ldg(xr); a[0].y = 0.0f; }
        dft8(a, b);
        // stage-1 twiddle w1 = e^{2*pi*i*t/4096} = e0^4
        float2 e2 = cmul(e0, e0);
        twiddle8w(b, cmul(e2, e2));
    }
#pragma unroll
    for (int j = 0; j < 8; j++) buf[SKEW(t + 512 * j)] = b[j];
    __syncthreads();

    // ---- stage 2 (L = 512, stride 64) ----
    {
        const int B = (t >> 6) << 9, p = t & 63;
#pragma unroll
        for (int j = 0; j < 8; j++) a[j] = buf[SKEW(B + p + 64 * j)];
        dft8(a, b);
        float s1, c1;
        __sincosf((float)p * 1.2271846303085130e-2f, &s1, &c1);  // 2*pi/512
        twiddle8w(b, make_float2(c1, s1));
#pragma unroll
        for (int j = 0; j < 8; j++) buf[SKEW(B + p + 64 * j)] = b[j];
    }
    __syncthreads();

    // ---- stage 3 (L = 64, stride 8) ----
    {
        const int B = (t >> 3) << 6, p = t & 7;
#pragma unroll
        for (int j = 0; j < 8; j++) a[j] = buf[SKEW(B + p + 8 * j)];
        dft8(a, b);
        float s1, c1;
        __sincosf((float)p * 9.8174770424681038e-2f, &s1, &c1);  // 2*pi/64
        twiddle8w(b, make_float2(c1, s1));
#pragma unroll
        for (int j = 0; j < 8; j++) buf[SKEW(B + p + 8 * j)] = b[j];
    }
    __syncthreads();

    // ---- stage 4 (L = 8) fused with digit-reversal scatter ----
#pragma unroll
    for (int j = 0; j < 8; j++) a[j] = buf[SKEW(8 * t + j)];
    __syncthreads();                 // all stage-4 reads done before aliasing overwrite
    dft8(a, b);                      // no twiddles at L = 8

    // b[j].x = v at storage index 8t+j -> logical m = drev(8t+j) = base + 512j.
    // Scatter REAL parts into an aliased float buffer at logical index m,
    // XOR-swizzled: bank = ((t>>6)^(lane&7)) | (((lane>>3)&3)<<3) -> conflict-free.
    float* vre = (float*)buf;
    {
        const int base = 64 * (t & 7) + 8 * ((t >> 3) & 7) + (t >> 6);
#pragma unroll
        for (int j = 0; j < 8; j++) {
            int m = base + 512 * j;
            vre[SWZ(m)] = b[j].x;
        }
    }
    __syncthreads();

    // ---- gather pairs: thread t owns m = 4t..4t+3 (2048 pairs / 512 threads).
    // y_{2m} = v_m, y_{2m+1} = v_{N-1-m}  ->  y[8t..8t+7], two STG.128.
    float va[4], vb[4];
#pragma unroll
    for (int c = 0; c < 4; c++) va[c] = vre[SWZ(4 * t + c)];
#pragma unroll
    for (int c = 0; c < 4; c++) vb[c] = vre[SWZ(N_FFT - 1 - 4 * t - c)];

    float4* o4 = (float4*)(y + rowoff);
    o4[2 * t]     = make_float4(va[0], vb[0], va[1], vb[1]);
    o4[2 * t + 1] = make_float4(va[2], vb[2], va[3], vb[3]);
}

extern "C" void kernel_launch(void* const* d_in, const int* in_sizes, int n_in,
                              void* d_out, int out_size) {
    (void)n_in; (void)out_size;
    const float* x = (const float*)d_in[0];
    float*       y = (float*)d_out;
    int rows = in_sizes[0] / N_FFT;      // 4096 for this problem
    idct_fft_kernel<<<rows, THREADS>>>(x, y);
}

// round 8
// speedup vs baseline: 1.7810x; 1.4960x over previous
#include <cuda_runtime.h>
#include <cstdint>

#define N_FFT   4096
#define M_FFT   2048
#define THREADS 256
#define SKEW(i) ((i) + ((i) >> 4))
#define BUF_ELEMS (M_FFT + (M_FFT >> 4))   // 2176 float2 = 17408 B static smem
// bijective XOR swizzle for the scatter buffer (logical index in [0,2048))
#define SWZ2(m) ((m) ^ (((m) >> 3) & 7) ^ ((((m) >> 7) & 1) << 3))

__device__ __forceinline__ float2 cadd(float2 a, float2 b){ return make_float2(a.x+b.x, a.y+b.y); }
__device__ __forceinline__ float2 csub(float2 a, float2 b){ return make_float2(a.x-b.x, a.y-b.y); }
__device__ __forceinline__ float2 cmul(float2 a, float2 b){
    return make_float2(fmaf(a.x, b.x, -a.y*b.y), fmaf(a.x, b.y, a.y*b.x));
}
__device__ __forceinline__ float2 cmuli(float2 a){ return make_float2(-a.y, a.x); }   // *(+i)

// 8-point DFT core, omega8 = e^{+2*pi*i/8}  (positive-sign DFT)
__device__ __forceinline__ void dft8(const float2 a[8], float2 b[8]) {
    float2 t0 = cadd(a[0], a[4]);
    float2 t1 = csub(a[0], a[4]);
    float2 t2 = cadd(a[2], a[6]);
    float2 t3 = cmuli(csub(a[2], a[6]));
    float2 u0 = cadd(a[1], a[5]);
    float2 u1 = csub(a[1], a[5]);
    float2 u2 = cadd(a[3], a[7]);
    float2 u3 = cmuli(csub(a[3], a[7]));

    float2 E0 = cadd(t0, t2), E2 = csub(t0, t2);
    float2 E1 = cadd(t1, t3), E3 = csub(t1, t3);
    float2 O0 = cadd(u0, u2), O2 = csub(u0, u2);
    float2 O1 = cadd(u1, u3), O3 = csub(u1, u3);

    const float r = 0.7071067811865476f;
    float2 W1 = make_float2(r * (O1.x - O1.y),  r * (O1.x + O1.y));   // omega8^1 * O1
    float2 W2 = cmuli(O2);                                            // omega8^2 * O2
    float2 W3 = make_float2(-r * (O3.x + O3.y), r * (O3.x - O3.y));   // omega8^3 * O3

    b[0] = cadd(E0, O0); b[4] = csub(E0, O0);
    b[1] = cadd(E1, W1); b[5] = csub(E1, W1);
    b[2] = cadd(E2, W2); b[6] = csub(E2, W2);
    b[3] = cadd(E3, W3); b[7] = csub(E3, W3);
}

// 4-point DFT, positive sign (omega4 = +i), no twiddles
__device__ __forceinline__ void dft4(const float2 z[4], float2 w[4]) {
    float2 s02 = cadd(z[0], z[2]), d02 = csub(z[0], z[2]);
    float2 s13 = cadd(z[1], z[3]), d13 = cmuli(csub(z[1], z[3]));
    w[0] = cadd(s02, s13);
    w[1] = cadd(d02, d13);
    w[2] = csub(s02, s13);
    w[3] = csub(d02, d13);
}

// Apply twiddles b[j] *= w1^j using log-depth power generation.
__device__ __forceinline__ void twiddle8w(float2 b[8], float2 w1) {
    float2 w2 = cmul(w1, w1);
    float2 w3 = cmul(w2, w1);
    float2 w4 = cmul(w2, w2);
    float2 w5 = cmul(w3, w2);
    float2 w6 = cmul(w3, w3);
    float2 w7 = cmul(w4, w3);
    b[1] = cmul(b[1], w1);
    b[2] = cmul(b[2], w2);
    b[3] = cmul(b[3], w3);
    b[4] = cmul(b[4], w4);
    b[5] = cmul(b[5], w5);
    b[6] = cmul(b[6], w6);
    b[7] = cmul(b[7], w7);
}

__global__ void __launch_bounds__(THREADS, 4)
idct_fft_kernel(const float* __restrict__ x, float* __restrict__ y) {
    __shared__ float2 buf[BUF_ELEMS];
    const int t = threadIdx.x;
    const size_t rowoff = (size_t)blockIdx.x * N_FFT;
    const float* __restrict__ xr = x + rowoff;

    float2 a[8], b[8];

    // ---- prologue fused with stage 1 of DFT_2048 ----
    // V_k = e^{i*pi*k/8192}(x_k - i x_{4096-k});  V_0 = x_0 special.
    // Z_k = (V_k + V_{k+2048}) + i * e^{i*pi*k/2048} * (V_k - V_{k+2048}).
    // a[j] = Z_{t + 256 j};  stage-1 twiddle w1 = e^{2*pi*i*t/2048} = e0^8.
    float s0, c0;
    __sincosf((float)t * 3.8349519697141028e-4f, &s0, &c0);   // pi/8192
    const float2 e0 = make_float2(c0, s0);
    float2 f2 = cmul(e0, e0);
    float2 f4 = cmul(f2, f2);
    float2 f8 = cmul(f4, f4);                                 // e^{2*pi*i*t/2048}

    // E_j = e^{i*pi*j/32}
    const float EC[8] = { 1.0f, 0.9951847266721969f, 0.9807852804032304f,
                          0.9569403357322089f, 0.9238795325112868f,
                          0.8819212643483551f, 0.8314696123025452f,
                          0.7730104533627370f };
    const float ES[8] = { 0.0f, 0.0980171403295606f, 0.1950903220161283f,
                          0.2902846772544624f, 0.3826834323650898f,
                          0.4713967368259976f, 0.5555702330196022f,
                          0.6343932841636455f };
    const float R2 = 0.7071067811865476f;                     // e^{i*pi/4} component

#pragma unroll
    for (int j = 0; j < 8; j++) {
        int   k  = t + 256 * j;                               // 0..2047
        float xa = __ldg(xr + k);
        float xb = __ldg(xr + ((N_FFT - k) & (N_FFT - 1)));
        float xc = __ldg(xr + (k + 2048));
        float xd = __ldg(xr + (2048 - k));
        // e_k = e0 * E_j = e^{i*pi*k/8192}
        float ekx = fmaf(e0.x, EC[j], -e0.y * ES[j]);
        float eky = fmaf(e0.x, ES[j],  e0.y * EC[j]);
        // V_k
        float v1x = fmaf(ekx, xa,  eky * xb);
        float v1y = fmaf(eky, xa, -ekx * xb);
        if (t == 0 && j == 0) { v1x = xa; v1y = 0.0f; }       // V_0 = x_0
        // V_{k+2048}: phase e_k * e^{i*pi/4}
        float c2x = R2 * (ekx - eky);
        float c2y = R2 * (ekx + eky);
        float v2x = fmaf(c2x, xc,  c2y * xd);
        float v2y = fmaf(c2y, xc, -c2x * xd);
        // S = V_k + V_{k+M}, D = V_k - V_{k+M}
        float Sx = v1x + v2x, Sy = v1y + v2y;
        float Dx = v1x - v2x, Dy = v1y - v2y;
        // e4k = e_k^4 = e^{i*pi*k/2048}
        float2 ek  = make_float2(ekx, eky);
        float2 e2k = cmul(ek, ek);
        float2 e4k = cmul(e2k, e2k);
        float edx = fmaf(e4k.x, Dx, -e4k.y * Dy);
        float edy = fmaf(e4k.x, Dy,  e4k.y * Dx);
        a[j] = make_float2(Sx - edy, Sy + edx);               // Z = S + i*(e4k*D)
    }
    dft8(a, b);
    twiddle8w(b, f8);
#pragma unroll
    for (int j = 0; j < 8; j++) buf[SKEW(t + 256 * j)] = b[j];
    __syncthreads();

    // ---- stage 2 (L = 256, stride 32) ----
    {
        const int B = (t >> 5) << 8, p = t & 31;
#pragma unroll
        for (int j = 0; j < 8; j++) a[j] = buf[SKEW(B + p + 32 * j)];
        dft8(a, b);
        float s1, c1;
        __sincosf((float)p * 2.4543692606170259e-2f, &s1, &c1);   // 2*pi/256
        twiddle8w(b, make_float2(c1, s1));
#pragma unroll
        for (int j = 0; j < 8; j++) buf[SKEW(B + p + 32 * j)] = b[j];
    }
    __syncthreads();

    // ---- stage 3 (L = 32, stride 4) ----
    {
        const int B = (t >> 2) << 5, p = t & 3;
#pragma unroll
        for (int j = 0; j < 8; j++) a[j] = buf[SKEW(B + p + 4 * j)];
        dft8(a, b);
        float s1, c1;
        __sincosf((float)p * 1.9634954084936207e-1f, &s1, &c1);   // 2*pi/32
        twiddle8w(b, make_float2(c1, s1));
#pragma unroll
        for (int j = 0; j < 8; j++) buf[SKEW(B + p + 4 * j)] = b[j];
    }
    __syncthreads();

    // ---- stage 4 (radix-4, L = 4, no twiddles) on contiguous quads ----
#pragma unroll
    for (int j = 0; j < 8; j++) a[j] = buf[SKEW(8 * t + j)];
    __syncthreads();                 // stage-4 reads done before aliasing overwrite
    dft4(&a[0], &b[0]);
    dft4(&a[4], &b[4]);

    // storage s = 8t+u holds frequency m = base + 64*(u>>2) + 512*(u&3),
    // base = (t>>5) + 8*((t>>2)&7) + 128*(t&3).
    // Scatter full complex w into aliased float2 buffer at logical m (swizzled).
    float2* zb = buf;
    {
        const int base = (t >> 5) + (((t >> 2) & 7) << 3) + ((t & 3) << 7);
#pragma unroll
        for (int u = 0; u < 8; u++) {
            int m = base + ((u >> 2) << 6) + ((u & 3) << 9);
            zb[SWZ2(m)] = b[u];
        }
    }
    __syncthreads();

    // ---- epilogue: y[4j..4j+3] = (Re w_j, Im w_{2047-j}, Im w_j, Re w_{2047-j})
    // j = t + 256c -> fully coalesced float4 stores.
    float4* o4 = (float4*)(y + rowoff);
#pragma unroll
    for (int c = 0; c < 4; c++) {
        int    j  = t + 256 * c;
        float2 wj = zb[SWZ2(j)];
        float2 wm = zb[SWZ2(2047 - j)];
        o4[j] = make_float4(wj.x, wm.y, wj.y, wm.x);
    }
}

extern "C" void kernel_launch(void* const* d_in, const int* in_sizes, int n_in,
                              void* d_out, int out_size) {
    (void)n_in; (void)out_size;
    const float* x = (const float*)d_in[0];
    float*       y = (float*)d_out;
    int rows = in_sizes[0] / N_FFT;      // 4096 for this problem
    idct_fft_kernel<<<rows, THREADS>>>(x, y);
}

// round 9
// speedup vs baseline: 1.8260x; 1.0253x over previous
#include <cuda_runtime.h>
#include <cstdint>

#define N_FFT   4096
#define THREADS 256
// two-level additive skew: (i>>8) term de-conflicts the stride-64-group gather
// in the fused final stage; it is warp-uniform in stages 1-3 (no change there).
#define SKEW(i) ((i) + ((i) >> 4) + ((i) >> 8))
#define BUF_ELEMS 2184                 // SKEW(2047)=2181; 17472 B static smem

__device__ __forceinline__ float2 cadd(float2 a, float2 b){ return make_float2(a.x+b.x, a.y+b.y); }
__device__ __forceinline__ float2 csub(float2 a, float2 b){ return make_float2(a.x-b.x, a.y-b.y); }
__device__ __forceinline__ float2 cmul(float2 a, float2 b){
    return make_float2(fmaf(a.x, b.x, -a.y*b.y), fmaf(a.x, b.y, a.y*b.x));
}
__device__ __forceinline__ float2 cmuli(float2 a){ return make_float2(-a.y, a.x); }   // *(+i)

// 8-point DFT core, omega8 = e^{+2*pi*i/8}  (positive-sign DFT)
__device__ __forceinline__ void dft8(const float2 a[8], float2 b[8]) {
    float2 t0 = cadd(a[0], a[4]);
    float2 t1 = csub(a[0], a[4]);
    float2 t2 = cadd(a[2], a[6]);
    float2 t3 = cmuli(csub(a[2], a[6]));
    float2 u0 = cadd(a[1], a[5]);
    float2 u1 = csub(a[1], a[5]);
    float2 u2 = cadd(a[3], a[7]);
    float2 u3 = cmuli(csub(a[3], a[7]));

    float2 E0 = cadd(t0, t2), E2 = csub(t0, t2);
    float2 E1 = cadd(t1, t3), E3 = csub(t1, t3);
    float2 O0 = cadd(u0, u2), O2 = csub(u0, u2);
    float2 O1 = cadd(u1, u3), O3 = csub(u1, u3);

    const float r = 0.7071067811865476f;
    float2 W1 = make_float2(r * (O1.x - O1.y),  r * (O1.x + O1.y));   // omega8^1 * O1
    float2 W2 = cmuli(O2);                                            // omega8^2 * O2
    float2 W3 = make_float2(-r * (O3.x + O3.y), r * (O3.x - O3.y));   // omega8^3 * O3

    b[0] = cadd(E0, O0); b[4] = csub(E0, O0);
    b[1] = cadd(E1, W1); b[5] = csub(E1, W1);
    b[2] = cadd(E2, W2); b[6] = csub(E2, W2);
    b[3] = cadd(E3, W3); b[7] = csub(E3, W3);
}

// Apply twiddles b[j] *= w1^j using log-depth power generation.
__device__ __forceinline__ void twiddle8w(float2 b[8], float2 w1) {
    float2 w2 = cmul(w1, w1);
    float2 w3 = cmul(w2, w1);
    float2 w4 = cmul(w2, w2);
    float2 w5 = cmul(w3, w2);
    float2 w6 = cmul(w3, w3);
    float2 w7 = cmul(w4, w3);
    b[1] = cmul(b[1], w1);
    b[2] = cmul(b[2], w2);
    b[3] = cmul(b[3], w3);
    b[4] = cmul(b[4], w4);
    b[5] = cmul(b[5], w5);
    b[6] = cmul(b[6], w6);
    b[7] = cmul(b[7], w7);
}

// storage quad index of the length-4 group whose DFT outputs land at
// frequencies B + 512*d (d=0..3); inverse of the 3-stage DIF digit map.
__device__ __forceinline__ int grp(int B) {
    return 2 * (((B & 7) << 5) + (((B >> 3) & 7) << 2) + ((B >> 7) & 3))
           + ((B >> 6) & 1);
}

__global__ void __launch_bounds__(THREADS, 4)
idct_fft_kernel(const float* __restrict__ x, float* __restrict__ y) {
    __shared__ float2 buf[BUF_ELEMS];
    const int t = threadIdx.x;
    const size_t rowoff = (size_t)blockIdx.x * N_FFT;
    const float* __restrict__ xr = x + rowoff;

    float2 a[8], b[8];

    // ---- prologue fused with stage 1 of DFT_2048 ----
    // V_k = e^{i*pi*k/8192}(x_k - i x_{4096-k});  V_0 = x_0 special.
    // Z_k = (V_k + V_{k+2048}) + i * e^{i*pi*k/2048} * (V_k - V_{k+2048}).
    float s0, c0;
    __sincosf((float)t * 3.8349519697141028e-4f, &s0, &c0);   // pi/8192
    const float2 e0 = make_float2(c0, s0);
    float2 f2 = cmul(e0, e0);
    float2 f4 = cmul(f2, f2);                                 // e^{i*pi*t/2048}
    float2 f8 = cmul(f4, f4);                                 // e^{2*pi*i*t/2048}

    // E_j = e^{i*pi*j/32}
    const float EC[8] = { 1.0f, 0.9951847266721969f, 0.9807852804032304f,
                          0.9569403357322089f, 0.9238795325112868f,
                          0.8819212643483551f, 0.8314696123025452f,
                          0.7730104533627370f };
    const float ES[8] = { 0.0f, 0.0980171403295606f, 0.1950903220161283f,
                          0.2902846772544624f, 0.3826834323650898f,
                          0.4713967368259976f, 0.5555702330196022f,
                          0.6343932841636455f };
    // G_j = e^{i*pi*j/8}
    const float GC[8] = { 1.0f,  0.9238795325112868f,  0.7071067811865476f,
                          0.3826834323650898f,  0.0f, -0.3826834323650898f,
                         -0.7071067811865476f, -0.9238795325112868f };
    const float GS[8] = { 0.0f,  0.3826834323650898f,  0.7071067811865476f,
                          0.9238795325112868f,  1.0f,  0.9238795325112868f,
                          0.7071067811865476f,  0.3826834323650898f };
    const float R2 = 0.7071067811865476f;

#pragma unroll
    for (int j = 0; j < 8; j++) {
        int   k  = t + 256 * j;                               // 0..2047
        float xa = __ldg(xr + k);
        float xb = __ldg(xr + ((N_FFT - k) & (N_FFT - 1)));
        float xc = __ldg(xr + (k + 2048));
        float xd = __ldg(xr + (2048 - k));
        // e_k = e0 * E_j = e^{i*pi*k/8192}
        float ekx = fmaf(e0.x, EC[j], -e0.y * ES[j]);
        float eky = fmaf(e0.x, ES[j],  e0.y * EC[j]);
        // V_k
        float v1x = fmaf(ekx, xa,  eky * xb);
        float v1y = fmaf(eky, xa, -ekx * xb);
        if (t == 0 && j == 0) { v1x = xa; v1y = 0.0f; }       // V_0 = x_0
        // V_{k+2048}: phase e_k * e^{i*pi/4}
        float c2x = R2 * (ekx - eky);
        float c2y = R2 * (ekx + eky);
        float v2x = fmaf(c2x, xc,  c2y * xd);
        float v2y = fmaf(c2y, xc, -c2x * xd);
        float Sx = v1x + v2x, Sy = v1y + v2y;
        float Dx = v1x - v2x, Dy = v1y - v2y;
        // e4k = e^{i*pi*k/2048} = f4 * G_j
        float e4x = fmaf(f4.x, GC[j], -f4.y * GS[j]);
        float e4y = fmaf(f4.x, GS[j],  f4.y * GC[j]);
        float edx = fmaf(e4x, Dx, -e4y * Dy);
        float edy = fmaf(e4x, Dy,  e4y * Dx);
        a[j] = make_float2(Sx - edy, Sy + edx);               // Z = S + i*(e4k*D)
    }
    dft8(a, b);
    twiddle8w(b, f8);
#pragma unroll
    for (int j = 0; j < 8; j++) buf[SKEW(t + 256 * j)] = b[j];
    __syncthreads();

    // ---- stage 2 (L = 256, stride 32) ----
    {
        const int B = (t >> 5) << 8, p = t & 31;
#pragma unroll
        for (int j = 0; j < 8; j++) a[j] = buf[SKEW(B + p + 32 * j)];
        dft8(a, b);
        float s1, c1;
        __sincosf((float)p * 2.4543692606170259e-2f, &s1, &c1);   // 2*pi/256
        twiddle8w(b, make_float2(c1, s1));
#pragma unroll
        for (int j = 0; j < 8; j++) buf[SKEW(B + p + 32 * j)] = b[j];
    }
    __syncthreads();

    // ---- stage 3 (L = 32, stride 4) ----
    {
        const int B = (t >> 2) << 5, p = t & 3;
#pragma unroll
        for (int j = 0; j < 8; j++) a[j] = buf[SKEW(B + p + 4 * j)];
        dft8(a, b);
        float s1, c1;
        __sincosf((float)p * 1.9634954084936207e-1f, &s1, &c1);   // 2*pi/32
        twiddle8w(b, make_float2(c1, s1));
#pragma unroll
        for (int j = 0; j < 8; j++) buf[SKEW(B + p + 4 * j)] = b[j];
    }
    __syncthreads();

    // ---- fused stage 4 (radix-4, no twiddles) + epilogue ----
    // Group at quad grp(B) produces w_{B+512d} = dft4 output d.
    // Thread t needs: d0,d1 of B=t and B=t+256;  d2,d3 of B=511-t and B=255-t.
    float2 wt0, wt1, wu0, wu1, wm2, wm3, wn2, wn3;
    {
        int g = grp(t);
        float2 z0 = buf[SKEW(4*g)],   z1 = buf[SKEW(4*g+1)];
        float2 z2 = buf[SKEW(4*g+2)], z3 = buf[SKEW(4*g+3)];
        float2 s02 = cadd(z0, z2), s13 = cadd(z1, z3);
        float2 d02 = csub(z0, z2), d13 = cmuli(csub(z1, z3));
        wt0 = cadd(s02, s13);            // w_t
        wt1 = cadd(d02, d13);            // w_{t+512}
    }
    {
        int g = grp(t + 256);
        float2 z0 = buf[SKEW(4*g)],   z1 = buf[SKEW(4*g+1)];
        float2 z2 = buf[SKEW(4*g+2)], z3 = buf[SKEW(4*g+3)];
        float2 s02 = cadd(z0, z2), s13 = cadd(z1, z3);
        float2 d02 = csub(z0, z2), d13 = cmuli(csub(z1, z3));
        wu0 = cadd(s02, s13);            // w_{t+256}
        wu1 = cadd(d02, d13);            // w_{t+768}
    }
    {
        int g = grp(511 - t);
        float2 z0 = buf[SKEW(4*g)],   z1 = buf[SKEW(4*g+1)];
        float2 z2 = buf[SKEW(4*g+2)], z3 = buf[SKEW(4*g+3)];
        float2 s02 = cadd(z0, z2), s13 = cadd(z1, z3);
        float2 d02 = csub(z0, z2), d13 = cmuli(csub(z1, z3));
        wm2 = csub(s02, s13);            // w_{1535-t}
        wm3 = csub(d02, d13);            // w_{2047-t}
    }
    {
        int g = grp(255 - t);
        float2 z0 = buf[SKEW(4*g)],   z1 = buf[SKEW(4*g+1)];
        float2 z2 = buf[SKEW(4*g+2)], z3 = buf[SKEW(4*g+3)];
        float2 s02 = cadd(z0, z2), s13 = cadd(z1, z3);
        float2 d02 = csub(z0, z2), d13 = cmuli(csub(z1, z3));
        wn2 = csub(s02, s13);            // w_{1279-t}
        wn3 = csub(d02, d13);            // w_{1791-t}
    }

    // y[4j..4j+3] = (Re w_j, Im w_{2047-j}, Im w_j, Re w_{2047-j})
    float4* o4 = (float4*)(y + rowoff);
    o4[t      ] = make_float4(wt0.x, wm3.y, wt0.y, wm3.x);   // j = t
    o4[t + 256] = make_float4(wu0.x, wn3.y, wu0.y, wn3.x);   // j = t+256
    o4[t + 512] = make_float4(wt1.x, wm2.y, wt1.y, wm2.x);   // j = t+512
    o4[t + 768] = make_float4(wu1.x, wn2.y, wu1.y, wn2.x);   // j = t+768
}

extern "C" void kernel_launch(void* const* d_in, const int* in_sizes, int n_in,
                              void* d_out, int out_size) {
    (void)n_in; (void)out_size;
    const float* x = (const float*)d_in[0];
    float*       y = (float*)d_out;
    int rows = in_sizes[0] / N_FFT;      // 4096 for this problem
    idct_fft_kernel<<<rows, THREADS>>>(x, y);
}

// round 10
// speedup vs baseline: 2.0884x; 1.1437x over previous
#include <cuda_runtime.h>
#include <cstdint>

#define N_FFT   4096
#define THREADS 256
// even two-level skew: keeps quads {4g..4g+3} contiguous AND 16B-aligned so the
// fused final stage can read each group with LDS.128; conflict-free in all stages.
#define SKEW(i) ((i) + 2 * (((i) >> 4) + ((i) >> 8)))
#define BUF_ELEMS 2316                 // SKEW(2047)=2315; 18528 B static smem

__device__ __forceinline__ float2 cadd(float2 a, float2 b){ return make_float2(a.x+b.x, a.y+b.y); }
__device__ __forceinline__ float2 csub(float2 a, float2 b){ return make_float2(a.x-b.x, a.y-b.y); }
__device__ __forceinline__ float2 cmul(float2 a, float2 b){
    return make_float2(fmaf(a.x, b.x, -a.y*b.y), fmaf(a.x, b.y, a.y*b.x));
}
__device__ __forceinline__ float2 cmuli(float2 a){ return make_float2(-a.y, a.x); }   // *(+i)

// 8-point DFT core, omega8 = e^{+2*pi*i/8}  (positive-sign DFT)
__device__ __forceinline__ void dft8(const float2 a[8], float2 b[8]) {
    float2 t0 = cadd(a[0], a[4]);
    float2 t1 = csub(a[0], a[4]);
    float2 t2 = cadd(a[2], a[6]);
    float2 t3 = cmuli(csub(a[2], a[6]));
    float2 u0 = cadd(a[1], a[5]);
    float2 u1 = csub(a[1], a[5]);
    float2 u2 = cadd(a[3], a[7]);
    float2 u3 = cmuli(csub(a[3], a[7]));

    float2 E0 = cadd(t0, t2), E2 = csub(t0, t2);
    float2 E1 = cadd(t1, t3), E3 = csub(t1, t3);
    float2 O0 = cadd(u0, u2), O2 = csub(u0, u2);
    float2 O1 = cadd(u1, u3), O3 = csub(u1, u3);

    const float r = 0.7071067811865476f;
    float2 W1 = make_float2(r * (O1.x - O1.y),  r * (O1.x + O1.y));   // omega8^1 * O1
    float2 W2 = cmuli(O2);                                            // omega8^2 * O2
    float2 W3 = make_float2(-r * (O3.x + O3.y), r * (O3.x - O3.y));   // omega8^3 * O3

    b[0] = cadd(E0, O0); b[4] = csub(E0, O0);
    b[1] = cadd(E1, W1); b[5] = csub(E1, W1);
    b[2] = cadd(E2, W2); b[6] = csub(E2, W2);
    b[3] = cadd(E3, W3); b[7] = csub(E3, W3);
}

// Apply twiddles b[j] *= w1^j using log-depth power generation.
__device__ __forceinline__ void twiddle8w(float2 b[8], float2 w1) {
    float2 w2 = cmul(w1, w1);
    float2 w3 = cmul(w2, w1);
    float2 w4 = cmul(w2, w2);
    float2 w5 = cmul(w3, w2);
    float2 w6 = cmul(w3, w3);
    float2 w7 = cmul(w4, w3);
    b[1] = cmul(b[1], w1);
    b[2] = cmul(b[2], w2);
    b[3] = cmul(b[3], w3);
    b[4] = cmul(b[4], w4);
    b[5] = cmul(b[5], w5);
    b[6] = cmul(b[6], w6);
    b[7] = cmul(b[7], w7);
}

// storage quad index of the length-4 group whose DFT outputs land at
// frequencies B + 512*d (d=0..3); inverse of the 3-stage DIF digit map.
__device__ __forceinline__ int grp(int B) {
    return 2 * (((B & 7) << 5) + (((B >> 3) & 7) << 2) + ((B >> 7) & 3))
           + ((B >> 6) & 1);
}

__global__ void __launch_bounds__(THREADS, 4)
idct_fft_kernel(const float* __restrict__ x, float* __restrict__ y) {
    __shared__ __align__(16) float2 buf[BUF_ELEMS];
    const int t = threadIdx.x;
    const size_t rowoff = (size_t)blockIdx.x * N_FFT;
    const float* __restrict__ xr = x + rowoff;

    float2 a[8], b[8];

    // ---- prologue fused with stage 1 of DFT_2048 ----
    // V_k = e^{i*pi*k/8192}(x_k - i x_{4096-k});  V_0 = x_0 special.
    // Z_k = (V_k + V_{k+2048}) + i * e^{i*pi*k/2048} * (V_k - V_{k+2048}).
    float s0, c0;
    __sincosf((float)t * 3.8349519697141028e-4f, &s0, &c0);   // pi/8192
    const float2 e0 = make_float2(c0, s0);
    float2 f2 = cmul(e0, e0);
    float2 f4 = cmul(f2, f2);                                 // e^{i*pi*t/2048}
    float2 f8 = cmul(f4, f4);                                 // e^{2*pi*i*t/2048}

    // E_j = e^{i*pi*j/32}
    const float EC[8] = { 1.0f, 0.9951847266721969f, 0.9807852804032304f,
                          0.9569403357322089f, 0.9238795325112868f,
                          0.8819212643483551f, 0.8314696123025452f,
                          0.7730104533627370f };
    const float ES[8] = { 0.0f, 0.0980171403295606f, 0.1950903220161283f,
                          0.2902846772544624f, 0.3826834323650898f,
                          0.4713967368259976f, 0.5555702330196022f,
                          0.6343932841636455f };
    // G_j = e^{i*pi*j/8}
    const float GC[8] = { 1.0f,  0.9238795325112868f,  0.7071067811865476f,
                          0.3826834323650898f,  0.0f, -0.3826834323650898f,
                         -0.7071067811865476f, -0.9238795325112868f };
    const float GS[8] = { 0.0f,  0.3826834323650898f,  0.7071067811865476f,
                          0.9238795325112868f,  1.0f,  0.9238795325112868f,
                          0.7071067811865476f,  0.3826834323650898f };
    const float R2 = 0.7071067811865476f;

#pragma unroll
    for (int j = 0; j < 8; j++) {
        int   k  = t + 256 * j;                               // 0..2047
        float xa = __ldg(xr + k);
        float xb = __ldg(xr + ((N_FFT - k) & (N_FFT - 1)));
        float xc = __ldg(xr + (k + 2048));
        float xd = __ldg(xr + (2048 - k));
        // e_k = e0 * E_j = e^{i*pi*k/8192}
        float ekx = fmaf(e0.x, EC[j], -e0.y * ES[j]);
        float eky = fmaf(e0.x, ES[j],  e0.y * EC[j]);
        // V_k
        float v1x = fmaf(ekx, xa,  eky * xb);
        float v1y = fmaf(eky, xa, -ekx * xb);
        if (t == 0 && j == 0) { v1x = xa; v1y = 0.0f; }       // V_0 = x_0
        // V_{k+2048}: phase e_k * e^{i*pi/4}
        float c2x = R2 * (ekx - eky);
        float c2y = R2 * (ekx + eky);
        float v2x = fmaf(c2x, xc,  c2y * xd);
        float v2y = fmaf(c2y, xc, -c2x * xd);
        float Sx = v1x + v2x, Sy = v1y + v2y;
        float Dx = v1x - v2x, Dy = v1y - v2y;
        // e4k = e^{i*pi*k/2048} = f4 * G_j
        float e4x = fmaf(f4.x, GC[j], -f4.y * GS[j]);
        float e4y = fmaf(f4.x, GS[j],  f4.y * GC[j]);
        float edx = fmaf(e4x, Dx, -e4y * Dy);
        float edy = fmaf(e4x, Dy,  e4y * Dx);
        a[j] = make_float2(Sx - edy, Sy + edx);               // Z = S + i*(e4k*D)
    }
    dft8(a, b);
    twiddle8w(b, f8);
#pragma unroll
    for (int j = 0; j < 8; j++) buf[SKEW(t + 256 * j)] = b[j];
    __syncthreads();

    // ---- stage 2 (L = 256, stride 32) ----
    {
        const int B = (t >> 5) << 8, p = t & 31;
#pragma unroll
        for (int j = 0; j < 8; j++) a[j] = buf[SKEW(B + p + 32 * j)];
        dft8(a, b);
        float s1, c1;
        __sincosf((float)p * 2.4543692606170259e-2f, &s1, &c1);   // 2*pi/256
        twiddle8w(b, make_float2(c1, s1));
#pragma unroll
        for (int j = 0; j < 8; j++) buf[SKEW(B + p + 32 * j)] = b[j];
    }
    __syncthreads();

    // ---- stage 3 (L = 32, stride 4) ----
    {
        const int B = (t >> 2) << 5, p = t & 3;
#pragma unroll
        for (int j = 0; j < 8; j++) a[j] = buf[SKEW(B + p + 4 * j)];
        dft8(a, b);
        float s1, c1;
        __sincosf((float)p * 1.9634954084936207e-1f, &s1, &c1);   // 2*pi/32
        twiddle8w(b, make_float2(c1, s1));
#pragma unroll
        for (int j = 0; j < 8; j++) buf[SKEW(B + p + 4 * j)] = b[j];
    }
    __syncthreads();

    // ---- fused stage 4 (radix-4, no twiddles) + epilogue ----
    // Quad grp(B) holds the length-4 group whose dft4 outputs are w_{B+512d}.
    // Mirror identity: group 511-t produces exactly the mirrors of group t's
    // outputs, so ONE thread computing BOTH full dft4s owns all 8 w-values for
    // output rows j in {t, t+512, 511-t, 1023-t}.
    float2 wA[4], wB[4];
    {
        int g = grp(t);
        float4 q0 = *(const float4*)&buf[SKEW(4 * g)];
        float4 q1 = *(const float4*)&buf[SKEW(4 * g) + 2];
        float2 z0 = make_float2(q0.x, q0.y), z1 = make_float2(q0.z, q0.w);
        float2 z2 = make_float2(q1.x, q1.y), z3 = make_float2(q1.z, q1.w);
        float2 s02 = cadd(z0, z2), s13 = cadd(z1, z3);
        float2 d02 = csub(z0, z2), d13 = cmuli(csub(z1, z3));
        wA[0] = cadd(s02, s13);   // w_t
        wA[1] = cadd(d02, d13);   // w_{t+512}
        wA[2] = csub(s02, s13);   // w_{t+1024}
        wA[3] = csub(d02, d13);   // w_{t+1536}
    }
    {
        int g = grp(511 - t);
        float4 q0 = *(const float4*)&buf[SKEW(4 * g)];
        float4 q1 = *(const float4*)&buf[SKEW(4 * g) + 2];
        float2 z0 = make_float2(q0.x, q0.y), z1 = make_float2(q0.z, q0.w);
        float2 z2 = make_float2(q1.x, q1.y), z3 = make_float2(q1.z, q1.w);
        float2 s02 = cadd(z0, z2), s13 = cadd(z1, z3);
        float2 d02 = csub(z0, z2), d13 = cmuli(csub(z1, z3));
        wB[0] = cadd(s02, s13);   // w_{511-t}
        wB[1] = cadd(d02, d13);   // w_{1023-t}
        wB[2] = csub(s02, s13);   // w_{1535-t}
        wB[3] = csub(d02, d13);   // w_{2047-t}
    }

    // y[4j..4j+3] = (Re w_j, Im w_{2047-j}, Im w_j, Re w_{2047-j})
    float4* o4 = (float4*)(y + rowoff);
    o4[t       ] = make_float4(wA[0].x, wB[3].y, wA[0].y, wB[3].x);  // j = t
    o4[t + 512 ] = make_float4(wA[1].x, wB[2].y, wA[1].y, wB[2].x);  // j = t+512
    o4[511 - t ] = make_float4(wB[0].x, wA[3].y, wB[0].y, wA[3].x);  // j = 511-t
    o4[1023 - t] = make_float4(wB[1].x, wA[2].y, wB[1].y, wA[2].x);  // j = 1023-t
}

extern "C" void kernel_launch(void* const* d_in, const int* in_sizes, int n_in,
                              void* d_out, int out_size) {
    (void)n_in; (void)out_size;
    const float* x = (const float*)d_in[0];
    float*       y = (float*)d_out;
    int rows = in_sizes[0] / N_FFT;      // 4096 for this problem
    idct_fft_kernel<<<rows, THREADS>>>(x, y);
}